// round 2
// baseline (speedup 1.0000x reference)
#include <cuda_runtime.h>
#include <cstdint>

#define BB 64
#define NN 1024
#define IC 16
#define HC 64
#define OC 32

// Scratch (allocation-free rule: device globals)
__device__ float g_h  [BB * NN * HC];   // linear1 output
__device__ float g_h2 [BB * NN * HC];   // propagate1 output
__device__ float g_o1 [BB * NN * OC];   // linear2 output
__device__ float g_invdeg[BB * NN];     // 1/(deg+1), produced by propagate1

__device__ __forceinline__ float to_tf32(float x) {
    uint32_t u;
    asm("cvt.rna.tf32.f32 %0, %1;" : "=r"(u) : "f"(x));
    return __uint_as_float(u);
}

__device__ __forceinline__ void mma8(float c[4], const uint32_t a[4], const uint32_t b[2]) {
    asm volatile(
        "mma.sync.aligned.m16n8k8.row.col.f32.tf32.tf32.f32 "
        "{%0,%1,%2,%3}, {%4,%5,%6,%7}, {%8,%9}, {%0,%1,%2,%3};\n"
        : "+f"(c[0]), "+f"(c[1]), "+f"(c[2]), "+f"(c[3])
        : "r"(a[0]), "r"(a[1]), "r"(a[2]), "r"(a[3]), "r"(b[0]), "r"(b[1]));
}

// ---------------------------------------------------------------------------
// Linear 1: h = x @ W1^T + b1   ([B,N,16] -> [B,N,64])
// block = 256 threads, tile = 64 rows of one batch
// ---------------------------------------------------------------------------
__global__ void __launch_bounds__(256) k_lin1(const float* __restrict__ x,
                                              const float* __restrict__ W1,
                                              const float* __restrict__ b1) {
    __shared__ float xs[64][17];
    __shared__ float ws[64][16];   // W1[h][c], broadcast access -> no pad needed
    __shared__ float bs[64];

    int tile = blockIdx.x;
    int b = tile >> 4;
    int n0 = (tile & 15) * 64;
    int t = threadIdx.x;

    const float* xp = x + ((size_t)b * NN + n0) * IC;
    for (int i = t; i < 64 * 16; i += 256) xs[i >> 4][i & 15] = xp[i];
    for (int i = t; i < 64 * 16; i += 256) ws[i >> 4][i & 15] = W1[i];
    if (t < 64) bs[t] = b1[t];
    __syncthreads();

    int row = t & 63;
    int c0 = (t >> 6) * 16;
    float acc[16];
#pragma unroll
    for (int j = 0; j < 16; j++) acc[j] = bs[c0 + j];
#pragma unroll
    for (int c = 0; c < 16; c++) {
        float xv = xs[row][c];
#pragma unroll
        for (int j = 0; j < 16; j++) acc[j] += xv * ws[c0 + j][c];
    }
    float* hp = g_h + ((size_t)b * NN + n0 + row) * HC + c0;
#pragma unroll
    for (int j = 0; j < 16; j++) hp[j] = acc[j];
}

// ---------------------------------------------------------------------------
// Linear 2: o1 = h2 @ W2^T + b2   ([B,N,64] -> [B,N,32])
// ---------------------------------------------------------------------------
__global__ void __launch_bounds__(256) k_lin2(const float* __restrict__ W2,
                                              const float* __restrict__ b2) {
    __shared__ float hs[64][65];
    __shared__ float ws[32][64];   // broadcast access
    __shared__ float bs[32];

    int tile = blockIdx.x;
    int b = tile >> 4;
    int n0 = (tile & 15) * 64;
    int t = threadIdx.x;

    const float4* hp4 = (const float4*)(g_h2 + ((size_t)b * NN + n0) * HC);
    for (int j = t; j < 64 * 16; j += 256) {
        float4 v = hp4[j];
        int r = j >> 4, c = (j & 15) * 4;
        hs[r][c] = v.x; hs[r][c + 1] = v.y; hs[r][c + 2] = v.z; hs[r][c + 3] = v.w;
    }
    const float4* wp4 = (const float4*)W2;
    for (int j = t; j < 32 * 16; j += 256) {
        float4 v = wp4[j];
        int r = j >> 4, c = (j & 15) * 4;
        ws[r][c] = v.x; ws[r][c + 1] = v.y; ws[r][c + 2] = v.z; ws[r][c + 3] = v.w;
    }
    if (t < 32) bs[t] = b2[t];
    __syncthreads();

    int row = t & 63;
    int c0 = (t >> 6) * 8;
    float acc[8];
#pragma unroll
    for (int j = 0; j < 8; j++) acc[j] = bs[c0 + j];
#pragma unroll
    for (int c = 0; c < 64; c++) {
        float xv = hs[row][c];
#pragma unroll
        for (int j = 0; j < 8; j++) acc[j] += xv * ws[c0 + j][c];
    }
    float* op = g_o1 + ((size_t)b * NN + n0 + row) * OC + c0;
#pragma unroll
    for (int j = 0; j < 8; j++) op[j] = acc[j];
}

// ---------------------------------------------------------------------------
// Propagate: Out = relu((A_raw @ Hin + Hin_self) * inv_deg)
//   FIRST: C=64, BN=72 (col 64 = ones column computes deg via the MMA itself),
//          writes g_h2 + g_invdeg.
//   !FIRST: C=32, BN=32, reads g_invdeg, writes OutParam (d_out).
// BM=128 rows/CTA, BK=32, 4 warps * (32 rows x BN cols), tf32 m16n8k8.
// ---------------------------------------------------------------------------
template <int C, int BN, int HSTR, bool FIRST>
__global__ void __launch_bounds__(128) k_prop(const float* __restrict__ G,
                                              float* __restrict__ OutParam) {
    constexpr int BM = 128, BK = 32;
    constexpr int NT = BN / 8;        // n-tiles (incl. deg tile when FIRST)
    constexpr int NTO = C / 8;        // output n-tiles

    __shared__ float Gs[BM * 36];     // stride 36 (==4 mod 32): conflict-free A frags
    __shared__ float Hs[BK * HSTR];   // HSTR==8 mod 32: conflict-free B frags

    const int blk = blockIdx.x;
    const int b = blk >> 3;
    const int m0 = (blk & 7) * BM;

    const float* Gp = G + ((size_t)b * NN + m0) * NN;
    const float* Hin = FIRST ? g_h : g_o1;
    const float* Hp = Hin + (size_t)b * NN * C;
    float* Out = FIRST ? g_h2 : OutParam;

    const int t = threadIdx.x;
    const int warp = t >> 5;
    const int lane = t & 31;
    const int g4 = lane >> 2;
    const int tg = lane & 3;

    float acc[2][NT][4];
#pragma unroll
    for (int mt = 0; mt < 2; mt++)
#pragma unroll
        for (int nt = 0; nt < NT; nt++)
#pragma unroll
            for (int j = 0; j < 4; j++) acc[mt][nt][j] = 0.f;

    for (int k0 = 0; k0 < NN; k0 += BK) {
        // --- load G tile [BM x BK], convert to tf32 ---
        const float* gsrc = Gp + k0;
#pragma unroll
        for (int i = 0; i < 8; i++) {
            int row = (t >> 3) + i * 16;
            int kg = (t & 7) * 4;
            float4 v = *(const float4*)(gsrc + (size_t)row * NN + kg);
            int sb = row * 36 + kg;
            Gs[sb]     = to_tf32(v.x);
            Gs[sb + 1] = to_tf32(v.y);
            Gs[sb + 2] = to_tf32(v.z);
            Gs[sb + 3] = to_tf32(v.w);
        }
        // --- load H tile [BK x BN] (col C == ones column when FIRST) ---
        for (int i = t; i < BK * BN; i += 128) {
            int kk = i / BN;
            int n = i % BN;
            float v;
            if (n < C) v = Hp[(size_t)(k0 + kk) * C + n];
            else       v = (n == C) ? 1.0f : 0.0f;
            Hs[kk * HSTR + n] = to_tf32(v);
        }
        __syncthreads();

        // --- compute 4 k-steps of m16n8k8 ---
#pragma unroll
        for (int ks = 0; ks < BK / 8; ks++) {
            uint32_t afr[2][4];
#pragma unroll
            for (int mt = 0; mt < 2; mt++) {
                int rbase = (warp * 32 + mt * 16 + g4) * 36 + ks * 8 + tg;
                afr[mt][0] = __float_as_uint(Gs[rbase]);
                afr[mt][1] = __float_as_uint(Gs[rbase + 8 * 36]);
                afr[mt][2] = __float_as_uint(Gs[rbase + 4]);
                afr[mt][3] = __float_as_uint(Gs[rbase + 8 * 36 + 4]);
            }
#pragma unroll
            for (int nt = 0; nt < NT; nt++) {
                uint32_t bfr[2];
                bfr[0] = __float_as_uint(Hs[(ks * 8 + tg) * HSTR + nt * 8 + g4]);
                bfr[1] = __float_as_uint(Hs[(ks * 8 + tg + 4) * HSTR + nt * 8 + g4]);
                mma8(acc[0][nt], afr[0], bfr);
                mma8(acc[1][nt], afr[1], bfr);
            }
        }
        __syncthreads();
    }

    // --- epilogue: self-loop add, degree scale, relu ---
#pragma unroll
    for (int mt = 0; mt < 2; mt++) {
        int row0 = m0 + warp * 32 + mt * 16 + g4;
        int row1 = row0 + 8;
        float inv0, inv1;
        if (FIRST) {
            // deg sits in the last n-tile, col C (held by tg==0 lanes)
            float d0 = __shfl_sync(0xffffffffu, acc[mt][NT - 1][0], lane & ~3);
            float d1 = __shfl_sync(0xffffffffu, acc[mt][NT - 1][2], lane & ~3);
            inv0 = 1.0f / (d0 + 1.0f);
            inv1 = 1.0f / (d1 + 1.0f);
            if (tg == 0) {
                g_invdeg[(size_t)b * NN + row0] = inv0;
                g_invdeg[(size_t)b * NN + row1] = inv1;
            }
        } else {
            inv0 = g_invdeg[(size_t)b * NN + row0];
            inv1 = g_invdeg[(size_t)b * NN + row1];
        }
#pragma unroll
        for (int nt = 0; nt < NTO; nt++) {
            int col = nt * 8 + 2 * tg;
            float2 s0 = *(const float2*)(Hin + ((size_t)b * NN + row0) * C + col);
            float2 s1 = *(const float2*)(Hin + ((size_t)b * NN + row1) * C + col);
            float2 r0, r1;
            r0.x = fmaxf((acc[mt][nt][0] + s0.x) * inv0, 0.f);
            r0.y = fmaxf((acc[mt][nt][1] + s0.y) * inv0, 0.f);
            r1.x = fmaxf((acc[mt][nt][2] + s1.x) * inv1, 0.f);
            r1.y = fmaxf((acc[mt][nt][3] + s1.y) * inv1, 0.f);
            *(float2*)(Out + ((size_t)b * NN + row0) * C + col) = r0;
            *(float2*)(Out + ((size_t)b * NN + row1) * C + col) = r1;
        }
    }
}

extern "C" void kernel_launch(void* const* d_in, const int* in_sizes, int n_in,
                              void* d_out, int out_size) {
    const float* x     = (const float*)d_in[0];
    const float* graph = (const float*)d_in[1];
    const float* W1    = (const float*)d_in[2];
    const float* b1    = (const float*)d_in[3];
    const float* W2    = (const float*)d_in[4];
    const float* b2    = (const float*)d_in[5];
    float* out = (float*)d_out;

    k_lin1<<<BB * NN / 64, 256>>>(x, W1, b1);
    k_prop<HC, 72, 72, true><<<BB * 8, 128>>>(graph, nullptr);
    k_lin2<<<BB * NN / 64, 256>>>(W2, b2);
    k_prop<OC, 32, 40, false><<<BB * 8, 128>>>(graph, out);
}

// round 6
// speedup vs baseline: 1.9419x; 1.9419x over previous
#include <cuda_runtime.h>
#include <cstdint>

#define BB 64
#define NN 1024
#define IC 16
#define HC 64
#define OC 32

// Scratch (allocation-free rule: device globals)
__device__ float g_h  [BB * NN * HC];   // linear1 output
__device__ float g_h2 [BB * NN * HC];   // propagate1 output
__device__ float g_o1 [BB * NN * OC];   // linear2 output
__device__ float g_invdeg[BB * NN];     // 1/(deg+1), produced by propagate1

__device__ __forceinline__ void mma8(float c[4], const uint32_t a[4], const uint32_t b[2]) {
    asm volatile(
        "mma.sync.aligned.m16n8k8.row.col.f32.tf32.tf32.f32 "
        "{%0,%1,%2,%3}, {%4,%5,%6,%7}, {%8,%9}, {%0,%1,%2,%3};\n"
        : "+f"(c[0]), "+f"(c[1]), "+f"(c[2]), "+f"(c[3])
        : "r"(a[0]), "r"(a[1]), "r"(a[2]), "r"(a[3]), "r"(b[0]), "r"(b[1]));
}

__device__ __forceinline__ void ldgsts16(uint32_t dst, const float* src) {
    asm volatile("cp.async.cg.shared.global [%0], [%1], 16;\n" :: "r"(dst), "l"(src));
}

// ---------------------------------------------------------------------------
// Linear 1: h = x @ W1^T + b1   ([B,N,16] -> [B,N,64])
// ---------------------------------------------------------------------------
__global__ void __launch_bounds__(256) k_lin1(const float* __restrict__ x,
                                              const float* __restrict__ W1,
                                              const float* __restrict__ b1) {
    __shared__ float xs[64][17];
    __shared__ float ws[64][16];
    __shared__ float bs[64];

    int tile = blockIdx.x;
    int b = tile >> 4;
    int n0 = (tile & 15) * 64;
    int t = threadIdx.x;

    const float* xp = x + ((size_t)b * NN + n0) * IC;
    for (int i = t; i < 64 * 16; i += 256) xs[i >> 4][i & 15] = xp[i];
    for (int i = t; i < 64 * 16; i += 256) ws[i >> 4][i & 15] = W1[i];
    if (t < 64) bs[t] = b1[t];
    __syncthreads();

    int row = t & 63;
    int c0 = (t >> 6) * 16;
    float acc[16];
#pragma unroll
    for (int j = 0; j < 16; j++) acc[j] = bs[c0 + j];
#pragma unroll
    for (int c = 0; c < 16; c++) {
        float xv = xs[row][c];
#pragma unroll
        for (int j = 0; j < 16; j++) acc[j] += xv * ws[c0 + j][c];
    }
    float* hp = g_h + ((size_t)b * NN + n0 + row) * HC + c0;
#pragma unroll
    for (int j = 0; j < 16; j++) hp[j] = acc[j];
}

// ---------------------------------------------------------------------------
// Linear 2: o1 = h2 @ W2^T + b2   ([B,N,64] -> [B,N,32])
// ---------------------------------------------------------------------------
__global__ void __launch_bounds__(256) k_lin2(const float* __restrict__ W2,
                                              const float* __restrict__ b2) {
    __shared__ float hs[64][65];
    __shared__ float ws[32][64];
    __shared__ float bs[32];

    int tile = blockIdx.x;
    int b = tile >> 4;
    int n0 = (tile & 15) * 64;
    int t = threadIdx.x;

    const float4* hp4 = (const float4*)(g_h2 + ((size_t)b * NN + n0) * HC);
    for (int j = t; j < 64 * 16; j += 256) {
        float4 v = hp4[j];
        int r = j >> 4, c = (j & 15) * 4;
        hs[r][c] = v.x; hs[r][c + 1] = v.y; hs[r][c + 2] = v.z; hs[r][c + 3] = v.w;
    }
    const float4* wp4 = (const float4*)W2;
    for (int j = t; j < 32 * 16; j += 256) {
        float4 v = wp4[j];
        int r = j >> 4, c = (j & 15) * 4;
        ws[r][c] = v.x; ws[r][c + 1] = v.y; ws[r][c + 2] = v.z; ws[r][c + 3] = v.w;
    }
    if (t < 32) bs[t] = b2[t];
    __syncthreads();

    int row = t & 63;
    int c0 = (t >> 6) * 8;
    float acc[8];
#pragma unroll
    for (int j = 0; j < 8; j++) acc[j] = bs[c0 + j];
#pragma unroll
    for (int c = 0; c < 64; c++) {
        float xv = hs[row][c];
#pragma unroll
        for (int j = 0; j < 8; j++) acc[j] += xv * ws[c0 + j][c];
    }
    float* op = g_o1 + ((size_t)b * NN + n0 + row) * OC + c0;
#pragma unroll
    for (int j = 0; j < 8; j++) op[j] = acc[j];
}

// ---------------------------------------------------------------------------
// Propagate: Out = relu((A_raw @ Hin + Hin_self) * inv_deg)
//  Conservative 2-stage cp.async double buffer (wait_group + 2 barriers/iter).
//  G tile [128x32] fp32, XOR-swizzled 128B rows. H tile [32xC] padded to HSTR
//  (pad holds ones column -> MMA computes degree for free when FIRST).
//  FIRST  (prop1): 256 thr; warps 0-3 = cols 0..31, warps 4-7 = cols 32..71
//                  (tile 8 = degree). Writes g_h2 + g_invdeg.
//  !FIRST (prop2): 256 thr; 8 M-warps x 16 rows, cols 0..31 -> d_out.
// ---------------------------------------------------------------------------
template <int C, int HSTR, bool FIRST>
__global__ void __launch_bounds__(256) k_prop(const float* __restrict__ G,
                                              float* __restrict__ OutParam) {
    constexpr int BM = 128, BK = 32, S = 2;
    constexpr int GS_STG = BM * BK;               // 4096 floats/stage
    constexpr int HS_STG = BK * HSTR;
    constexpr int NTMAX = FIRST ? 5 : 4;
    constexpr int MT = FIRST ? 2 : 1;             // m-tiles per warp
    constexpr int NITER = NN / BK;                // 32
    constexpr int HCH = BK * (C / 4);             // H 16B chunks per tile

    extern __shared__ float smem[];
    float* Gs = smem;                              // [S][GS_STG]
    float* Hs = smem + S * GS_STG;                 // [S][HS_STG]
    float* invs = Hs + S * HS_STG;                 // [128]

    const int blk = blockIdx.x;
    const int b = blk >> 3;
    const int m0 = (blk & 7) * BM;

    const float* Gp = G + ((size_t)b * NN + m0) * NN;
    const float* Hin = FIRST ? g_h : g_o1;
    const float* Hp = Hin + (size_t)b * NN * C;
    float* Out = FIRST ? g_h2 : OutParam;

    const int t = threadIdx.x;
    const int warp = t >> 5;
    const int lane = t & 31;
    const int g4 = lane >> 2;
    const int tg = lane & 3;
    const int mw = FIRST ? (warp & 3) : warp;     // m-warp index
    const int grp = FIRST ? (warp >> 2) : 0;      // n-group
    const int ntbase = grp * 4;
    const int NTg = FIRST ? (grp ? 5 : 4) : 4;

    const uint32_t gs_u = (uint32_t)__cvta_generic_to_shared(Gs);
    const uint32_t hs_u = (uint32_t)__cvta_generic_to_shared(Hs);

    // constant pad init (ones/deg column lives at col C when FIRST)
    for (int i = t; i < S * BK * (HSTR - C); i += 256) {
        int s = i / (BK * (HSTR - C));
        int r = (i / (HSTR - C)) % BK;
        int c = i % (HSTR - C);
        Hs[s * HS_STG + r * HSTR + C + c] = (FIRST && c == 0) ? 1.0f : 0.0f;
    }

    float acc[MT][NTMAX][4];
#pragma unroll
    for (int mt = 0; mt < MT; mt++)
#pragma unroll
        for (int nt = 0; nt < NTMAX; nt++)
#pragma unroll
            for (int j = 0; j < 4; j++) acc[mt][nt][j] = 0.f;

    // ---- prologue: load tile 0 into stage 0 ----
#pragma unroll
    for (int i = 0; i < 4; ++i) {                 // G: 1024 chunks / 256 thr
        int idx = t + i * 256;
        int r = idx >> 3, c = idx & 7;
        ldgsts16(gs_u + (uint32_t)(r * BK + ((c ^ (r & 7)) << 2)) * 4u,
                 Gp + (size_t)r * NN + c * 4);
    }
#pragma unroll
    for (int i = 0; i < HCH / 256; ++i) {         // H
        int idx = t + i * 256;
        int r = idx / (C / 4), c = idx % (C / 4);
        ldgsts16(hs_u + (uint32_t)(r * HSTR + c * 4) * 4u,
                 Hp + (size_t)r * C + c * 4);
    }
    asm volatile("cp.async.commit_group;\n");

    for (int it = 0; it < NITER; ++it) {
        // issue loads for it+1 into stage (it+1)&1
        if (it + 1 < NITER) {
            const int k0 = (it + 1) * BK;
            const int stg = (it + 1) & 1;
#pragma unroll
            for (int i = 0; i < 4; ++i) {
                int idx = t + i * 256;
                int r = idx >> 3, c = idx & 7;
                ldgsts16(gs_u + (uint32_t)(stg * GS_STG + r * BK + ((c ^ (r & 7)) << 2)) * 4u,
                         Gp + (size_t)r * NN + k0 + c * 4);
            }
#pragma unroll
            for (int i = 0; i < HCH / 256; ++i) {
                int idx = t + i * 256;
                int r = idx / (C / 4), c = idx % (C / 4);
                ldgsts16(hs_u + (uint32_t)(stg * HS_STG + r * HSTR + c * 4) * 4u,
                         Hp + (size_t)(k0 + r) * C + c * 4);
            }
        }
        asm volatile("cp.async.commit_group;\n");
        // stage `it` is complete once at most 1 (the just-committed) group pends
        asm volatile("cp.async.wait_group 1;\n");
        __syncthreads();

        const float* Gb = Gs + (it & 1) * GS_STG;
        const float* Hb = Hs + (it & 1) * HS_STG;
#pragma unroll
        for (int ks = 0; ks < BK / 8; ++ks) {
            uint32_t afr[MT][4];
#pragma unroll
            for (int mt = 0; mt < MT; ++mt) {
                int r0 = FIRST ? (mw * 32 + mt * 16 + g4) : (mw * 16 + g4);
                int base  = r0 * BK + (((2 * ks)     ^ (r0 & 7)) << 2) + tg;
                int base2 = r0 * BK + (((2 * ks + 1) ^ (r0 & 7)) << 2) + tg;
                afr[mt][0] = __float_as_uint(Gb[base]);
                afr[mt][1] = __float_as_uint(Gb[base + 8 * BK]);
                afr[mt][2] = __float_as_uint(Gb[base2]);
                afr[mt][3] = __float_as_uint(Gb[base2 + 8 * BK]);
            }
#pragma unroll
            for (int nt = 0; nt < NTMAX; ++nt) {
                if (nt < NTg) {
                    int n = (ntbase + nt) * 8 + g4;
                    uint32_t bfr[2];
                    bfr[0] = __float_as_uint(Hb[(ks * 8 + tg) * HSTR + n]);
                    bfr[1] = __float_as_uint(Hb[(ks * 8 + tg + 4) * HSTR + n]);
#pragma unroll
                    for (int mt = 0; mt < MT; ++mt) mma8(acc[mt][nt], afr[mt], bfr);
                }
            }
        }
        // all reads of this stage done before it is overwritten next iteration
        __syncthreads();
    }

    // --- epilogue ---
    if (FIRST) {
        if (grp == 1) {
#pragma unroll
            for (int mt = 0; mt < MT; ++mt) {
                float d0 = __shfl_sync(0xffffffffu, acc[mt][NTMAX - 1][0], lane & ~3);
                float d1 = __shfl_sync(0xffffffffu, acc[mt][NTMAX - 1][2], lane & ~3);
                float i0 = 1.0f / (d0 + 1.0f);
                float i1 = 1.0f / (d1 + 1.0f);
                int rl = mw * 32 + mt * 16 + g4;
                if (tg == 0) {
                    invs[rl] = i0;
                    invs[rl + 8] = i1;
                    g_invdeg[(size_t)b * NN + m0 + rl] = i0;
                    g_invdeg[(size_t)b * NN + m0 + rl + 8] = i1;
                }
            }
        }
        __syncthreads();
    }

#pragma unroll
    for (int mt = 0; mt < MT; ++mt) {
        int rl = FIRST ? (mw * 32 + mt * 16 + g4) : (mw * 16 + g4);
        int row0 = m0 + rl;
        int row1 = row0 + 8;
        float inv0, inv1;
        if (FIRST) { inv0 = invs[rl]; inv1 = invs[rl + 8]; }
        else {
            inv0 = g_invdeg[(size_t)b * NN + row0];
            inv1 = g_invdeg[(size_t)b * NN + row1];
        }
#pragma unroll
        for (int nt = 0; nt < 4; ++nt) {          // 4 output n-tiles per group
            int col = (ntbase + nt) * 8 + 2 * tg;
            float2 s0 = *(const float2*)(Hin + ((size_t)b * NN + row0) * C + col);
            float2 s1 = *(const float2*)(Hin + ((size_t)b * NN + row1) * C + col);
            float2 r0, r1;
            r0.x = fmaxf((acc[mt][nt][0] + s0.x) * inv0, 0.f);
            r0.y = fmaxf((acc[mt][nt][1] + s0.y) * inv0, 0.f);
            r1.x = fmaxf((acc[mt][nt][2] + s1.x) * inv1, 0.f);
            r1.y = fmaxf((acc[mt][nt][3] + s1.y) * inv1, 0.f);
            *(float2*)(Out + ((size_t)b * NN + row0) * C + col) = r0;
            *(float2*)(Out + ((size_t)b * NN + row1) * C + col) = r1;
        }
    }
}

extern "C" void kernel_launch(void* const* d_in, const int* in_sizes, int n_in,
                              void* d_out, int out_size) {
    const float* x     = (const float*)d_in[0];
    const float* graph = (const float*)d_in[1];
    const float* W1    = (const float*)d_in[2];
    const float* b1    = (const float*)d_in[3];
    const float* W2    = (const float*)d_in[4];
    const float* b2    = (const float*)d_in[5];
    float* out = (float*)d_out;

    constexpr int SM1 = (2 * 4096 + 2 * 32 * 72 + 128) * 4;   // 51712 B
    constexpr int SM2 = (2 * 4096 + 2 * 32 * 40 + 128) * 4;   // 43520 B
    cudaFuncSetAttribute(k_prop<HC, 72, true>,
                         cudaFuncAttributeMaxDynamicSharedMemorySize, SM1);
    cudaFuncSetAttribute(k_prop<OC, 40, false>,
                         cudaFuncAttributeMaxDynamicSharedMemorySize, SM2);

    k_lin1<<<BB * NN / 64, 256>>>(x, W1, b1);
    k_prop<HC, 72, true><<<BB * 8, 256, SM1>>>(graph, nullptr);
    k_lin2<<<BB * NN / 64, 256>>>(W2, b2);
    k_prop<OC, 40, false><<<BB * 8, 256, SM2>>>(graph, out);
}